// round 9
// baseline (speedup 1.0000x reference)
#include <cuda_runtime.h>
#include <math.h>

#define B   32
#define T   64
#define S   400
#define DW  512
#define DM  512
#define DE  512
#define DK  64
#define G3  (3*DM)          // 1536
#define PAD_ID 50256

// ---------------- scratch (device globals) ------------------------------------
__device__ float g_emb[T*B*DW];       // [T,B,DW]
__device__ float g_pre[B*S*DK];       // enc @ Wc
__device__ float g_h  [B*DM];
__device__ float g_ctx[B*DE];
__device__ float g_cov[B*S];
__device__ float g_gxp[16][B*G3];     // gx split-K partials
__device__ float g_ghp[8][B*G3];      // gh split-K partials
__device__ float g_rop[24][B*DM];     // readout split-K partials

// out layout (float32):
#define OFF_PRED      0
#define OFF_ATTNLAST  524288
#define OFF_CTXF      537088
#define OFF_COPY      553472
#define OFF_GATE      1372672
#define OFF_COVP      1374720

__device__ __forceinline__ float tanh_fast(float x) {
    float y; asm("tanh.approx.f32 %0, %1;" : "=f"(y) : "f"(x)); return y;
}
__device__ __forceinline__ float sigmoid_fast(float x) {
    return 1.f / (1.f + __expf(-x));
}

// block reductions for 512 threads (16 warps), via shuffles. sred[16].
__device__ __forceinline__ float bsum(float v, float* sred, int tid) {
    __syncthreads();                       // protect sred reuse
#pragma unroll
    for (int o = 16; o > 0; o >>= 1) v += __shfl_xor_sync(~0u, v, o);
    if ((tid & 31) == 0) sred[tid >> 5] = v;
    __syncthreads();
    if (tid < 32) {
        float x = (tid < 16) ? sred[tid] : 0.f;
#pragma unroll
        for (int o = 8; o > 0; o >>= 1) x += __shfl_xor_sync(~0u, x, o);
        if (tid == 0) sred[0] = x;
    }
    __syncthreads();
    return sred[0];
}
__device__ __forceinline__ float bmax(float v, float* sred, int tid) {
    __syncthreads();
#pragma unroll
    for (int o = 16; o > 0; o >>= 1) v = fmaxf(v, __shfl_xor_sync(~0u, v, o));
    if ((tid & 31) == 0) sred[tid >> 5] = v;
    __syncthreads();
    if (tid < 32) {
        float x = (tid < 16) ? sred[tid] : -1e30f;
#pragma unroll
        for (int o = 8; o > 0; o >>= 1) x = fmaxf(x, __shfl_xor_sync(~0u, x, o));
        if (tid == 0) sred[0] = x;
    }
    __syncthreads();
    return sred[0];
}

// ---------------- one-time kernels -------------------------------------------

__global__ void k_embed(const int* __restrict__ tgt, const float* __restrict__ word_emb)
{
    int row = blockIdx.x;                 // row = t*B + b
    int t = row / B, b = row % B;
    int id = tgt[b*T + t];
    const float4* src = (const float4*)(word_emb + (long long)id * DW);
    float4* dst = (float4*)(g_emb + (long long)row * DW);
    dst[threadIdx.x] = src[threadIdx.x];  // 128 threads * float4
}

__global__ void k_pre(const float* __restrict__ enc, const float* __restrict__ Wc)
{
    int row = blockIdx.x * 16 + threadIdx.y;        // grid 800, block (16,16)
    int n   = threadIdx.x * 4;
    const float* a = enc + (long long)row * DE;
    float4 acc = make_float4(0.f,0.f,0.f,0.f);
#pragma unroll 8
    for (int k = 0; k < DE; k++) {
        float av = a[k];
        float4 wv = *(const float4*)(Wc + k*DK + n);
        acc.x = fmaf(av, wv.x, acc.x); acc.y = fmaf(av, wv.y, acc.y);
        acc.z = fmaf(av, wv.z, acc.z); acc.w = fmaf(av, wv.w, acc.w);
    }
    *(float4*)(g_pre + (long long)row*DK + n) = acc;
}

__global__ void k_init(const float* __restrict__ hidden,
                       const float* __restrict__ W_init,
                       const float* __restrict__ b_init)
{
    int idx = blockIdx.x * 256 + threadIdx.x;   // 0..16383
    int b = idx / DM, j = idx % DM;
    const float* a = hidden + b * DE;
    float acc = b_init[j];
#pragma unroll 8
    for (int k = 0; k < DE; k++)
        acc = fmaf(a[k], W_init[k*DM + j], acc);
    g_h[idx]   = tanhf(acc);
    g_ctx[idx] = 0.f;
    if (idx < B*S) g_cov[idx] = 0.f;
}

// ---------------- per-step GEMM kernel (1536 blocks) --------------------------
// block (8,16) = 128 thr: tx -> 4 n-cols, ty -> 2 batch rows. K-chunk 64.
// bid [0,768):     gx  48 n-tiles x 16 k-chunks (Wx, K=1024)
// bid [768,1152):  gh  48 n-tiles x  8 k-chunks (Wh, K=512)
// bid [1152,1536): ro  16 n-tiles x 24 k-chunks (W_read, K=1536) for step t-1
__global__ void k_big(int t,
                      const float* __restrict__ Wx, const float* __restrict__ Wh,
                      const float* __restrict__ W_read)
{
    __shared__ float sAct[32][68];

    int bid = blockIdx.x;
    int tx = threadIdx.x;      // 0..7
    int ty = threadIdx.y;      // 0..15
    int tid = ty*8 + tx;

    const float* W; int n0, k0, stride, ks, mode;
    if (bid < 768) {
        if (t >= T) return;
        mode = 0; ks = bid & 15; n0 = (bid >> 4) * 32; k0 = ks * 64;
        W = Wx; stride = G3;
    } else if (bid < 1152) {
        if (t >= T) return;
        int r = bid - 768;
        mode = 1; ks = r & 7; n0 = (r >> 3) * 32; k0 = ks * 64;
        W = Wh; stride = G3;
    } else {
        if (t == 0) return;
        int r = bid - 1152;
        mode = 2; ks = r % 24; n0 = (r / 24) * 32; k0 = ks * 64;
        W = W_read; stride = DM;
    }

    // cooperative load of act chunk [32][64] (512 float4 / 128 thr = 4 each)
#pragma unroll
    for (int j = 0; j < 4; j++) {
        int f   = tid + j * 128;
        int row = f >> 4;
        int col = (f & 15) * 4;
        int kg  = k0 + col;
        const float* src;
        if (mode == 0) {
            src = (kg < 512) ? g_emb + ((size_t)t*B + row)*DW + kg
                             : g_ctx + row*DE + (kg - 512);
        } else if (mode == 1) {
            src = g_h + row*DM + kg;
        } else {
            if (kg < 512)       src = g_emb + ((size_t)(t-1)*B + row)*DW + kg;
            else if (kg < 1024) src = g_h   + row*DM + (kg - 512);
            else                src = g_ctx + row*DE + (kg - 1024);
        }
        *(float4*)&sAct[row][col] = *(const float4*)src;
    }
    __syncthreads();

    int n  = n0 + tx * 4;
    int b0 = ty * 2;
    const float* wp = W + (size_t)k0 * stride + n;
    float4 a0 = make_float4(0.f,0.f,0.f,0.f);
    float4 a1 = make_float4(0.f,0.f,0.f,0.f);

#pragma unroll 4
    for (int k = 0; k < 64; k += 4) {
        float4 x0 = *(const float4*)&sAct[b0][k];
        float4 x1 = *(const float4*)&sAct[b0+1][k];
        float4 w0 = *(const float4*)(wp + (size_t)(k  ) * stride);
        float4 w1 = *(const float4*)(wp + (size_t)(k+1) * stride);
        float4 w2 = *(const float4*)(wp + (size_t)(k+2) * stride);
        float4 w3 = *(const float4*)(wp + (size_t)(k+3) * stride);
        a0.x = fmaf(x0.x,w0.x,a0.x); a0.y = fmaf(x0.x,w0.y,a0.y);
        a0.z = fmaf(x0.x,w0.z,a0.z); a0.w = fmaf(x0.x,w0.w,a0.w);
        a1.x = fmaf(x1.x,w0.x,a1.x); a1.y = fmaf(x1.x,w0.y,a1.y);
        a1.z = fmaf(x1.x,w0.z,a1.z); a1.w = fmaf(x1.x,w0.w,a1.w);
        a0.x = fmaf(x0.y,w1.x,a0.x); a0.y = fmaf(x0.y,w1.y,a0.y);
        a0.z = fmaf(x0.y,w1.z,a0.z); a0.w = fmaf(x0.y,w1.w,a0.w);
        a1.x = fmaf(x1.y,w1.x,a1.x); a1.y = fmaf(x1.y,w1.y,a1.y);
        a1.z = fmaf(x1.y,w1.z,a1.z); a1.w = fmaf(x1.y,w1.w,a1.w);
        a0.x = fmaf(x0.z,w2.x,a0.x); a0.y = fmaf(x0.z,w2.y,a0.y);
        a0.z = fmaf(x0.z,w2.z,a0.z); a0.w = fmaf(x0.z,w2.w,a0.w);
        a1.x = fmaf(x1.z,w2.x,a1.x); a1.y = fmaf(x1.z,w2.y,a1.y);
        a1.z = fmaf(x1.z,w2.z,a1.z); a1.w = fmaf(x1.z,w2.w,a1.w);
        a0.x = fmaf(x0.w,w3.x,a0.x); a0.y = fmaf(x0.w,w3.y,a0.y);
        a0.z = fmaf(x0.w,w3.z,a0.z); a0.w = fmaf(x0.w,w3.w,a0.w);
        a1.x = fmaf(x1.w,w3.x,a1.x); a1.y = fmaf(x1.w,w3.y,a1.y);
        a1.z = fmaf(x1.w,w3.z,a1.z); a1.w = fmaf(x1.w,w3.w,a1.w);
    }

    if (mode == 0) {
        *(float4*)(g_gxp[ks] + (size_t)b0*G3 + n)     = a0;
        *(float4*)(g_gxp[ks] + (size_t)(b0+1)*G3 + n) = a1;
    } else if (mode == 1) {
        *(float4*)(g_ghp[ks] + (size_t)b0*G3 + n)     = a0;
        *(float4*)(g_ghp[ks] + (size_t)(b0+1)*G3 + n) = a1;
    } else {
        *(float4*)(g_rop[ks] + (size_t)b0*DM + n)     = a0;
        *(float4*)(g_rop[ks] + (size_t)(b0+1)*DM + n) = a1;
    }
}

// ---------------- per-step attention megakernel (512 thr / batch row) ---------
__global__ void k_attn(int t,
                       const int*   __restrict__ src_seq,
                       const float* __restrict__ enc,
                       const float* __restrict__ Wq,
                       const float* __restrict__ w_cov,
                       const float* __restrict__ v_att,
                       const float* __restrict__ W_copy,
                       const float* __restrict__ b_copy,
                       const float* __restrict__ bx,
                       const float* __restrict__ bh,
                       const float* __restrict__ b_read,
                       float* __restrict__ out)
{
    int b   = blockIdx.x;
    int tid = threadIdx.x;                 // 0..511

    __shared__ float sh[DM];
    __shared__ float sq[DK];
    __shared__ float sqp[8][DK];
    __shared__ float swc[DK];
    __shared__ float sva[DK];
    __shared__ float ss[S];
    __shared__ float sred[16];
    __shared__ float sctx[DE];
    __shared__ float spart[3][DE];

    // ---- readout reduce + maxout for step t-1 (independent side phase) ----
    if (t > 0 && tid < 256) {
        float2 acc = *(const float2*)(b_read + tid*2);
#pragma unroll
        for (int p = 0; p < 24; p++) {
            float2 v = *(const float2*)(g_rop[p] + (size_t)b*DM + tid*2);
            acc.x += v.x; acc.y += v.y;
        }
        out[OFF_PRED + ((size_t)b*T + (t-1)) * (DM/2) + tid] = fmaxf(acc.x, acc.y);
    }

    // ---- GRU gates -> h_new ----
    {
        int j = tid;
        size_t base = (size_t)b*G3 + j;
        float gxr = bx[j],        ghr = bh[j];
        float gxz = bx[DM+j],     ghz = bh[DM+j];
        float gxn = bx[2*DM+j],   ghn = bh[2*DM+j];
#pragma unroll
        for (int p = 0; p < 16; p++) {
            gxr += g_gxp[p][base];
            gxz += g_gxp[p][base + DM];
            gxn += g_gxp[p][base + 2*DM];
        }
#pragma unroll
        for (int p = 0; p < 8; p++) {
            ghr += g_ghp[p][base];
            ghz += g_ghp[p][base + DM];
            ghn += g_ghp[p][base + 2*DM];
        }
        float r  = sigmoid_fast(gxr + ghr);
        float z  = sigmoid_fast(gxz + ghz);
        float nn = tanh_fast(gxn + r * ghn);
        float ho = g_h[b*DM + j];
        float hn = (1.f - z) * nn + z * ho;
        sh[j] = hn;
        g_h[b*DM + j] = hn;
    }
    __syncthreads();

    // ---- q = h_new @ Wq  (split-K over 8 parts of 64) ----
    {
        int j = tid & 63, p = tid >> 6;     // p 0..7
        float acc = 0.f;
#pragma unroll 8
        for (int k = p*64; k < (p+1)*64; k++)
            acc = fmaf(sh[k], Wq[k*DK + j], acc);
        sqp[p][j] = acc;
        if (tid < DK)          swc[tid]      = w_cov[tid];
        else if (tid < 2*DK)   sva[tid - DK] = v_att[tid - DK];
    }
    __syncthreads();
    if (tid < DK) {
        float s = 0.f;
#pragma unroll
        for (int p = 0; p < 8; p++) s += sqp[p][tid];
        sq[tid] = s;
    }
    __syncthreads();

    // ---- attention scores with coverage + pad mask ----
    float cv = 0.f;
    if (tid < S) {
        cv = g_cov[b*S + tid];
        const float4* pr = (const float4*)(g_pre + ((size_t)b*S + tid) * DK);
        float acc = 0.f;
#pragma unroll
        for (int k4 = 0; k4 < 16; k4++) {
            float4 p = pr[k4];
            int k = k4*4;
            acc = fmaf(tanh_fast(p.x + sq[k  ] + cv*swc[k  ]), sva[k  ], acc);
            acc = fmaf(tanh_fast(p.y + sq[k+1] + cv*swc[k+1]), sva[k+1], acc);
            acc = fmaf(tanh_fast(p.z + sq[k+2] + cv*swc[k+2]), sva[k+2], acc);
            acc = fmaf(tanh_fast(p.w + sq[k+3] + cv*swc[k+3]), sva[k+3], acc);
        }
        if (src_seq[b*S + tid] == PAD_ID) acc = -1e9f;
        ss[tid] = acc;
    }

    // ---- softmax over S ----
    float m = bmax((tid < S) ? ss[tid] : -1e30f, sred, tid);
    float e = 0.f;
    if (tid < S) { e = __expf(ss[tid] - m); }
    float inv = 1.f / bsum(e, sred, tid);

    // ---- attn, coverage update, outputs ----
    float cl = 0.f;
    float tden = fmaxf((float)t, 1.f);
    if (tid < S) {
        float a = e * inv; ss[tid] = a;
        cl = fminf(a, cv / tden);
        g_cov[b*S + tid] = cv + a;
        out[OFF_COPY + (size_t)b*T*S + (size_t)t*S + tid] = a;
        if (t == T-1) out[OFF_ATTNLAST + b*S + tid] = a;
    }
    float clsum = bsum(cl, sred, tid);
    if (tid == 0) out[OFF_COVP + b*T + t] = clsum;
    __syncthreads();

    // ---- new_ctx = attn @ enc  (128 float4 cols x 4 s-slices of 100) ----
    {
        int d4 = tid & 127;
        int q  = tid >> 7;                      // 0..3
        const float4* e4 = (const float4*)(enc + (size_t)b*S*DE);
        float4 acc = make_float4(0.f,0.f,0.f,0.f);
        int s0 = q * 100;
        for (int i = 0; i < 25; i++) {
            int s = s0 + i*4;
            float a0s = ss[s],   a1s = ss[s+1];
            float a2s = ss[s+2], a3s = ss[s+3];
            float4 v0 = e4[(size_t)(s  )*(DE/4) + d4];
            float4 v1 = e4[(size_t)(s+1)*(DE/4) + d4];
            float4 v2 = e4[(size_t)(s+2)*(DE/4) + d4];
            float4 v3 = e4[(size_t)(s+3)*(DE/4) + d4];
            acc.x = fmaf(a0s,v0.x,acc.x); acc.y = fmaf(a0s,v0.y,acc.y);
            acc.z = fmaf(a0s,v0.z,acc.z); acc.w = fmaf(a0s,v0.w,acc.w);
            acc.x = fmaf(a1s,v1.x,acc.x); acc.y = fmaf(a1s,v1.y,acc.y);
            acc.z = fmaf(a1s,v1.z,acc.z); acc.w = fmaf(a1s,v1.w,acc.w);
            acc.x = fmaf(a2s,v2.x,acc.x); acc.y = fmaf(a2s,v2.y,acc.y);
            acc.z = fmaf(a2s,v2.z,acc.z); acc.w = fmaf(a2s,v2.w,acc.w);
            acc.x = fmaf(a3s,v3.x,acc.x); acc.y = fmaf(a3s,v3.y,acc.y);
            acc.z = fmaf(a3s,v3.z,acc.z); acc.w = fmaf(a3s,v3.w,acc.w);
        }
        if (q > 0) *(float4*)(&spart[q-1][d4*4]) = acc;
        __syncthreads();
        if (q == 0) {
#pragma unroll
            for (int p = 0; p < 3; p++) {
                float4 v = *(float4*)(&spart[p][d4*4]);
                acc.x += v.x; acc.y += v.y; acc.z += v.z; acc.w += v.w;
            }
            *(float4*)(&sctx[d4*4]) = acc;
            *(float4*)(g_ctx + b*DE + d4*4) = acc;
            if (t == T-1)
                *(float4*)(out + OFF_CTXF + b*DE + d4*4) = acc;
        }
        __syncthreads();
    }

    // ---- copy_gate = sigmoid([h_new, new_ctx] @ W_copy + b_copy) ----
    {
        float g = sh[tid] * W_copy[tid] + sctx[tid] * W_copy[DM + tid];
        float gs = bsum(g, sred, tid);
        if (tid == 0)
            out[OFF_GATE + b*T + t] = sigmoid_fast(gs + b_copy[0]);
    }
}

// final readout reduce for t = T-1
__global__ void k_rofin(const float* __restrict__ b_read, float* __restrict__ out)
{
    int b = blockIdx.x, tid = threadIdx.x;   // 32 blocks x 256
    float2 acc = *(const float2*)(b_read + tid*2);
#pragma unroll
    for (int p = 0; p < 24; p++) {
        float2 v = *(const float2*)(g_rop[p] + (size_t)b*DM + tid*2);
        acc.x += v.x; acc.y += v.y;
    }
    out[OFF_PRED + ((size_t)b*T + (T-1)) * (DM/2) + tid] = fmaxf(acc.x, acc.y);
}

// ---------------- launch ------------------------------------------------------

extern "C" void kernel_launch(void* const* d_in, const int* in_sizes, int n_in,
                              void* d_out, int out_size)
{
    const int*   tgt      = (const int*)  d_in[0];
    const int*   src      = (const int*)  d_in[1];
    const float* enc      = (const float*)d_in[2];
    const float* hidden   = (const float*)d_in[3];
    const float* word_emb = (const float*)d_in[4];
    const float* W_init   = (const float*)d_in[5];
    const float* b_init   = (const float*)d_in[6];
    const float* Wx       = (const float*)d_in[7];
    const float* Wh       = (const float*)d_in[8];
    const float* bx       = (const float*)d_in[9];
    const float* bh       = (const float*)d_in[10];
    const float* Wc       = (const float*)d_in[11];
    const float* Wq       = (const float*)d_in[12];
    const float* w_cov    = (const float*)d_in[13];
    const float* v_att    = (const float*)d_in[14];
    const float* W_copy   = (const float*)d_in[15];
    const float* b_copy   = (const float*)d_in[16];
    const float* W_read   = (const float*)d_in[17];
    const float* b_read   = (const float*)d_in[18];
    float* out = (float*)d_out;

    k_embed<<<T*B, 128>>>(tgt, word_emb);
    k_pre<<<(B*S)/16, dim3(16,16)>>>(enc, Wc);
    k_init<<<(B*DM)/256, 256>>>(hidden, W_init, b_init);

    for (int t = 0; t < T; t++) {
        k_big<<<1536, dim3(8,16)>>>(t, Wx, Wh, W_read);
        k_attn<<<B, 512>>>(t, src, enc, Wq, w_cov, v_att, W_copy, b_copy,
                           bx, bh, b_read, out);
    }
    k_big<<<1536, dim3(8,16)>>>(T, Wx, Wh, W_read);   // readout for t=T-1
    k_rofin<<<B, 256>>>(b_read, out);
}

// round 10
// speedup vs baseline: 1.3127x; 1.3127x over previous
#include <cuda_runtime.h>
#include <math.h>

#define B   32
#define T   64
#define S   400
#define DW  512
#define DM  512
#define DE  512
#define DK  64
#define G3  (3*DM)          // 1536
#define BDM (B*DM)          // 16384
#define PAD_ID 50256

// ---------------- scratch (device globals) ------------------------------------
__device__ float g_emb[T*B*DW];        // [T,B,DW]
__device__ float g_pre[B*S*DK];        // enc @ Wc
__device__ float g_hh[(T+1)*BDM];      // h history: slot t = h before step t
__device__ float g_cc[(T+1)*BDM];      // ctx history
__device__ float g_cov[B*S];
__device__ float g_gxp[8][B*G3];       // gx split-K partials
__device__ float g_ghp[4][B*G3];       // gh split-K partials
__device__ float g_rop[12][BDM];       // readout split-K partials

// out layout (float32):
#define OFF_PRED      0
#define OFF_ATTNLAST  524288
#define OFF_CTXF      537088
#define OFF_COPY      553472
#define OFF_GATE      1372672
#define OFF_COVP      1374720

__device__ __forceinline__ float tanh_fast(float x) {
    float y; asm("tanh.approx.f32 %0, %1;" : "=f"(y) : "f"(x)); return y;
}
__device__ __forceinline__ float sigmoid_fast(float x) {
    return 1.f / (1.f + __expf(-x));
}

// block reductions for 512 threads (16 warps), via shuffles. sred[16].
__device__ __forceinline__ float bsum(float v, float* sred, int tid) {
    __syncthreads();
#pragma unroll
    for (int o = 16; o > 0; o >>= 1) v += __shfl_xor_sync(~0u, v, o);
    if ((tid & 31) == 0) sred[tid >> 5] = v;
    __syncthreads();
    if (tid < 32) {
        float x = (tid < 16) ? sred[tid] : 0.f;
#pragma unroll
        for (int o = 8; o > 0; o >>= 1) x += __shfl_xor_sync(~0u, x, o);
        if (tid == 0) sred[0] = x;
    }
    __syncthreads();
    return sred[0];
}
__device__ __forceinline__ float bmax(float v, float* sred, int tid) {
    __syncthreads();
#pragma unroll
    for (int o = 16; o > 0; o >>= 1) v = fmaxf(v, __shfl_xor_sync(~0u, v, o));
    if ((tid & 31) == 0) sred[tid >> 5] = v;
    __syncthreads();
    if (tid < 32) {
        float x = (tid < 16) ? sred[tid] : -1e30f;
#pragma unroll
        for (int o = 8; o > 0; o >>= 1) x = fmaxf(x, __shfl_xor_sync(~0u, x, o));
        if (tid == 0) sred[0] = x;
    }
    __syncthreads();
    return sred[0];
}

// ---------------- one-time kernels -------------------------------------------

__global__ void k_embed(const int* __restrict__ tgt, const float* __restrict__ word_emb)
{
    int row = blockIdx.x;                 // row = t*B + b
    int t = row / B, b = row % B;
    int id = tgt[b*T + t];
    const float4* src = (const float4*)(word_emb + (long long)id * DW);
    float4* dst = (float4*)(g_emb + (long long)row * DW);
    dst[threadIdx.x] = src[threadIdx.x];
}

__global__ void k_pre(const float* __restrict__ enc, const float* __restrict__ Wc)
{
    int row = blockIdx.x * 16 + threadIdx.y;        // grid 800, block (16,16)
    int n   = threadIdx.x * 4;
    const float* a = enc + (long long)row * DE;
    float4 acc = make_float4(0.f,0.f,0.f,0.f);
#pragma unroll 8
    for (int k = 0; k < DE; k++) {
        float av = a[k];
        float4 wv = *(const float4*)(Wc + k*DK + n);
        acc.x = fmaf(av, wv.x, acc.x); acc.y = fmaf(av, wv.y, acc.y);
        acc.z = fmaf(av, wv.z, acc.z); acc.w = fmaf(av, wv.w, acc.w);
    }
    *(float4*)(g_pre + (long long)row*DK + n) = acc;
}

__global__ void k_init(const float* __restrict__ hidden,
                       const float* __restrict__ W_init,
                       const float* __restrict__ b_init)
{
    int idx = blockIdx.x * 256 + threadIdx.x;   // 0..16383
    int b = idx / DM, j = idx % DM;
    const float* a = hidden + b * DE;
    float acc = b_init[j];
#pragma unroll 8
    for (int k = 0; k < DE; k++)
        acc = fmaf(a[k], W_init[k*DM + j], acc);
    g_hh[idx] = tanhf(acc);       // slot 0
    g_cc[idx] = 0.f;              // slot 0
    if (idx < B*S) g_cov[idx] = 0.f;
}

// ---------------- per-step gx/gh GEMM kernel (576 blocks) ---------------------
// block (8,16) = 128 thr: tx -> 4 n-cols, ty -> 2 batch rows. K-chunk 128.
// bid [0,384):   gx  48 n-tiles x 8 k-chunks (Wx, K=1024)  acts: [emb(t), ctx(t)]
// bid [384,576): gh  48 n-tiles x 4 k-chunks (Wh, K=512)   acts: h(t)
__global__ void k_big(int t,
                      const float* __restrict__ Wx, const float* __restrict__ Wh)
{
    __shared__ float sAct[32][132];

    int bid = blockIdx.x;
    int tx = threadIdx.x;      // 0..7
    int ty = threadIdx.y;      // 0..15
    int tid = ty*8 + tx;

    const float* W; int n0, k0, ks, mode;
    if (bid < 384) {
        mode = 0; ks = bid & 7; n0 = (bid >> 3) * 32; k0 = ks * 128;
        W = Wx;
    } else {
        int r = bid - 384;
        mode = 1; ks = r & 3; n0 = (r >> 2) * 32; k0 = ks * 128;
        W = Wh;
    }

    // cooperative load of act chunk [32][128]
#pragma unroll
    for (int j = 0; j < 8; j++) {
        int f   = tid + j * 128;
        int row = f >> 5;
        int col = (f & 31) * 4;
        int kg  = k0 + col;
        const float* src;
        if (mode == 0) {
            src = (kg < 512) ? g_emb + ((size_t)t*B + row)*DW + kg
                             : g_cc + (size_t)t*BDM + row*DE + (kg - 512);
        } else {
            src = g_hh + (size_t)t*BDM + row*DM + kg;
        }
        *(float4*)&sAct[row][col] = *(const float4*)src;
    }
    __syncthreads();

    int n  = n0 + tx * 4;
    int b0 = ty * 2;
    const float* wp = W + (size_t)k0 * G3 + n;
    float4 a0 = make_float4(0.f,0.f,0.f,0.f);
    float4 a1 = make_float4(0.f,0.f,0.f,0.f);

#pragma unroll 4
    for (int k = 0; k < 128; k += 4) {
        float4 x0 = *(const float4*)&sAct[b0][k];
        float4 x1 = *(const float4*)&sAct[b0+1][k];
        float4 w0 = *(const float4*)(wp + (size_t)(k  ) * G3);
        float4 w1 = *(const float4*)(wp + (size_t)(k+1) * G3);
        float4 w2 = *(const float4*)(wp + (size_t)(k+2) * G3);
        float4 w3 = *(const float4*)(wp + (size_t)(k+3) * G3);
        a0.x = fmaf(x0.x,w0.x,a0.x); a0.y = fmaf(x0.x,w0.y,a0.y);
        a0.z = fmaf(x0.x,w0.z,a0.z); a0.w = fmaf(x0.x,w0.w,a0.w);
        a1.x = fmaf(x1.x,w0.x,a1.x); a1.y = fmaf(x1.x,w0.y,a1.y);
        a1.z = fmaf(x1.x,w0.z,a1.z); a1.w = fmaf(x1.x,w0.w,a1.w);
        a0.x = fmaf(x0.y,w1.x,a0.x); a0.y = fmaf(x0.y,w1.y,a0.y);
        a0.z = fmaf(x0.y,w1.z,a0.z); a0.w = fmaf(x0.y,w1.w,a0.w);
        a1.x = fmaf(x1.y,w1.x,a1.x); a1.y = fmaf(x1.y,w1.y,a1.y);
        a1.z = fmaf(x1.y,w1.z,a1.z); a1.w = fmaf(x1.y,w1.w,a1.w);
        a0.x = fmaf(x0.z,w2.x,a0.x); a0.y = fmaf(x0.z,w2.y,a0.y);
        a0.z = fmaf(x0.z,w2.z,a0.z); a0.w = fmaf(x0.z,w2.w,a0.w);
        a1.x = fmaf(x1.z,w2.x,a1.x); a1.y = fmaf(x1.z,w2.y,a1.y);
        a1.z = fmaf(x1.z,w2.z,a1.z); a1.w = fmaf(x1.z,w2.w,a1.w);
        a0.x = fmaf(x0.w,w3.x,a0.x); a0.y = fmaf(x0.w,w3.y,a0.y);
        a0.z = fmaf(x0.w,w3.z,a0.z); a0.w = fmaf(x0.w,w3.w,a0.w);
        a1.x = fmaf(x1.w,w3.x,a1.x); a1.y = fmaf(x1.w,w3.y,a1.y);
        a1.z = fmaf(x1.w,w3.z,a1.z); a1.w = fmaf(x1.w,w3.w,a1.w);
    }

    if (mode == 0) {
        *(float4*)(g_gxp[ks] + (size_t)b0*G3 + n)     = a0;
        *(float4*)(g_gxp[ks] + (size_t)(b0+1)*G3 + n) = a1;
    } else {
        *(float4*)(g_ghp[ks] + (size_t)b0*G3 + n)     = a0;
        *(float4*)(g_ghp[ks] + (size_t)(b0+1)*G3 + n) = a1;
    }
}

// ---------------- readout GEMM for step t (192 blocks; off critical path) -----
// block (8,16). ks = bid%12, n0 = (bid/12)*32. K=1536 split into 12 chunks of 128.
// acts: [emb(t), h(t+1), ctx(t+1)]
__global__ void k_ro(int t, const float* __restrict__ W_read)
{
    __shared__ float sAct[32][132];

    int bid = blockIdx.x;
    int tx = threadIdx.x;
    int ty = threadIdx.y;
    int tid = ty*8 + tx;

    int ks = bid % 12;
    int n0 = (bid / 12) * 32;
    int k0 = ks * 128;

#pragma unroll
    for (int j = 0; j < 8; j++) {
        int f   = tid + j * 128;
        int row = f >> 5;
        int col = (f & 31) * 4;
        int kg  = k0 + col;
        const float* src;
        if (kg < 512)       src = g_emb + ((size_t)t*B + row)*DW + kg;
        else if (kg < 1024) src = g_hh + (size_t)(t+1)*BDM + row*DM + (kg - 512);
        else                src = g_cc + (size_t)(t+1)*BDM + row*DE + (kg - 1024);
        *(float4*)&sAct[row][col] = *(const float4*)src;
    }
    __syncthreads();

    int n  = n0 + tx * 4;
    int b0 = ty * 2;
    const float* wp = W_read + (size_t)k0 * DM + n;
    float4 a0 = make_float4(0.f,0.f,0.f,0.f);
    float4 a1 = make_float4(0.f,0.f,0.f,0.f);

#pragma unroll 4
    for (int k = 0; k < 128; k += 4) {
        float4 x0 = *(const float4*)&sAct[b0][k];
        float4 x1 = *(const float4*)&sAct[b0+1][k];
        float4 w0 = *(const float4*)(wp + (size_t)(k  ) * DM);
        float4 w1 = *(const float4*)(wp + (size_t)(k+1) * DM);
        float4 w2 = *(const float4*)(wp + (size_t)(k+2) * DM);
        float4 w3 = *(const float4*)(wp + (size_t)(k+3) * DM);
        a0.x = fmaf(x0.x,w0.x,a0.x); a0.y = fmaf(x0.x,w0.y,a0.y);
        a0.z = fmaf(x0.x,w0.z,a0.z); a0.w = fmaf(x0.x,w0.w,a0.w);
        a1.x = fmaf(x1.x,w0.x,a1.x); a1.y = fmaf(x1.x,w0.y,a1.y);
        a1.z = fmaf(x1.x,w0.z,a1.z); a1.w = fmaf(x1.x,w0.w,a1.w);
        a0.x = fmaf(x0.y,w1.x,a0.x); a0.y = fmaf(x0.y,w1.y,a0.y);
        a0.z = fmaf(x0.y,w1.z,a0.z); a0.w = fmaf(x0.y,w1.w,a0.w);
        a1.x = fmaf(x1.y,w1.x,a1.x); a1.y = fmaf(x1.y,w1.y,a1.y);
        a1.z = fmaf(x1.y,w1.z,a1.z); a1.w = fmaf(x1.y,w1.w,a1.w);
        a0.x = fmaf(x0.z,w2.x,a0.x); a0.y = fmaf(x0.z,w2.y,a0.y);
        a0.z = fmaf(x0.z,w2.z,a0.z); a0.w = fmaf(x0.z,w2.w,a0.w);
        a1.x = fmaf(x1.z,w2.x,a1.x); a1.y = fmaf(x1.z,w2.y,a1.y);
        a1.z = fmaf(x1.z,w2.z,a1.z); a1.w = fmaf(x1.z,w2.w,a1.w);
        a0.x = fmaf(x0.w,w3.x,a0.x); a0.y = fmaf(x0.w,w3.y,a0.y);
        a0.z = fmaf(x0.w,w3.z,a0.z); a0.w = fmaf(x0.w,w3.w,a0.w);
        a1.x = fmaf(x1.w,w3.x,a1.x); a1.y = fmaf(x1.w,w3.y,a1.y);
        a1.z = fmaf(x1.w,w3.z,a1.z); a1.w = fmaf(x1.w,w3.w,a1.w);
    }

    *(float4*)(g_rop[ks] + (size_t)b0*DM + n)     = a0;
    *(float4*)(g_rop[ks] + (size_t)(b0+1)*DM + n) = a1;
}

// readout reduce + maxout for step t (off critical path)
__global__ void k_rored(int t, const float* __restrict__ b_read, float* __restrict__ out)
{
    int b = blockIdx.x, tid = threadIdx.x;   // 32 blocks x 256
    float2 acc = *(const float2*)(b_read + tid*2);
#pragma unroll
    for (int p = 0; p < 12; p++) {
        float2 v = *(const float2*)(g_rop[p] + (size_t)b*DM + tid*2);
        acc.x += v.x; acc.y += v.y;
    }
    out[OFF_PRED + ((size_t)b*T + t) * (DM/2) + tid] = fmaxf(acc.x, acc.y);
}

// ---------------- per-step attention megakernel (512 thr / batch row) ---------
__global__ void k_attn(int t,
                       const int*   __restrict__ src_seq,
                       const float* __restrict__ enc,
                       const float* __restrict__ Wq,
                       const float* __restrict__ w_cov,
                       const float* __restrict__ v_att,
                       const float* __restrict__ W_copy,
                       const float* __restrict__ b_copy,
                       const float* __restrict__ bx,
                       const float* __restrict__ bh,
                       float* __restrict__ out)
{
    int b   = blockIdx.x;
    int tid = threadIdx.x;                 // 0..511

    __shared__ float sh[DM];
    __shared__ float sq[DK];
    __shared__ float sqp[8][DK];
    __shared__ float swc[DK];
    __shared__ float sva[DK];
    __shared__ float ss[S];
    __shared__ float sred[16];
    __shared__ float sctx[DE];
    __shared__ float spart[3][DE];

    // ---- GRU gates -> h_new ----
    {
        int j = tid;
        size_t base = (size_t)b*G3 + j;
        float gxr = bx[j],        ghr = bh[j];
        float gxz = bx[DM+j],     ghz = bh[DM+j];
        float gxn = bx[2*DM+j],   ghn = bh[2*DM+j];
#pragma unroll
        for (int p = 0; p < 8; p++) {
            gxr += g_gxp[p][base];
            gxz += g_gxp[p][base + DM];
            gxn += g_gxp[p][base + 2*DM];
        }
#pragma unroll
        for (int p = 0; p < 4; p++) {
            ghr += g_ghp[p][base];
            ghz += g_ghp[p][base + DM];
            ghn += g_ghp[p][base + 2*DM];
        }
        float r  = sigmoid_fast(gxr + ghr);
        float z  = sigmoid_fast(gxz + ghz);
        float nn = tanh_fast(gxn + r * ghn);
        float ho = g_hh[(size_t)t*BDM + b*DM + j];
        float hn = (1.f - z) * nn + z * ho;
        sh[j] = hn;
        g_hh[(size_t)(t+1)*BDM + b*DM + j] = hn;
    }
    __syncthreads();

    // ---- q = h_new @ Wq  (split-K over 8 parts of 64) ----
    {
        int j = tid & 63, p = tid >> 6;     // p 0..7
        float acc = 0.f;
#pragma unroll 8
        for (int k = p*64; k < (p+1)*64; k++)
            acc = fmaf(sh[k], Wq[k*DK + j], acc);
        sqp[p][j] = acc;
        if (tid < DK)          swc[tid]      = w_cov[tid];
        else if (tid < 2*DK)   sva[tid - DK] = v_att[tid - DK];
    }
    __syncthreads();
    if (tid < DK) {
        float s = 0.f;
#pragma unroll
        for (int p = 0; p < 8; p++) s += sqp[p][tid];
        sq[tid] = s;
    }
    __syncthreads();

    // ---- attention scores with coverage + pad mask ----
    float cv = 0.f;
    if (tid < S) {
        cv = g_cov[b*S + tid];
        const float4* pr = (const float4*)(g_pre + ((size_t)b*S + tid) * DK);
        float acc = 0.f;
#pragma unroll
        for (int k4 = 0; k4 < 16; k4++) {
            float4 p = pr[k4];
            int k = k4*4;
            acc = fmaf(tanh_fast(p.x + sq[k  ] + cv*swc[k  ]), sva[k  ], acc);
            acc = fmaf(tanh_fast(p.y + sq[k+1] + cv*swc[k+1]), sva[k+1], acc);
            acc = fmaf(tanh_fast(p.z + sq[k+2] + cv*swc[k+2]), sva[k+2], acc);
            acc = fmaf(tanh_fast(p.w + sq[k+3] + cv*swc[k+3]), sva[k+3], acc);
        }
        if (src_seq[b*S + tid] == PAD_ID) acc = -1e9f;
        ss[tid] = acc;
    }

    // ---- softmax over S ----
    float m = bmax((tid < S) ? ss[tid] : -1e30f, sred, tid);
    float e = 0.f;
    if (tid < S) { e = __expf(ss[tid] - m); }
    float inv = 1.f / bsum(e, sred, tid);

    // ---- attn, coverage update, outputs ----
    float cl = 0.f;
    float tden = fmaxf((float)t, 1.f);
    if (tid < S) {
        float a = e * inv; ss[tid] = a;
        cl = fminf(a, cv / tden);
        g_cov[b*S + tid] = cv + a;
        out[OFF_COPY + (size_t)b*T*S + (size_t)t*S + tid] = a;
        if (t == T-1) out[OFF_ATTNLAST + b*S + tid] = a;
    }
    float clsum = bsum(cl, sred, tid);
    if (tid == 0) out[OFF_COVP + b*T + t] = clsum;
    __syncthreads();

    // ---- new_ctx = attn @ enc  (128 float4 cols x 4 s-slices of 100) ----
    {
        int d4 = tid & 127;
        int q  = tid >> 7;                      // 0..3
        const float4* e4 = (const float4*)(enc + (size_t)b*S*DE);
        float4 acc = make_float4(0.f,0.f,0.f,0.f);
        int s0 = q * 100, s1 = s0 + 100;
#pragma unroll 4
        for (int s = s0; s < s1; s++) {
            float a = ss[s];
            float4 v = e4[(size_t)s*(DE/4) + d4];
            acc.x = fmaf(a,v.x,acc.x); acc.y = fmaf(a,v.y,acc.y);
            acc.z = fmaf(a,v.z,acc.z); acc.w = fmaf(a,v.w,acc.w);
        }
        if (q > 0) *(float4*)(&spart[q-1][d4*4]) = acc;
        __syncthreads();
        if (q == 0) {
#pragma unroll
            for (int p = 0; p < 3; p++) {
                float4 v = *(float4*)(&spart[p][d4*4]);
                acc.x += v.x; acc.y += v.y; acc.z += v.z; acc.w += v.w;
            }
            *(float4*)(&sctx[d4*4]) = acc;
            *(float4*)(g_cc + (size_t)(t+1)*BDM + b*DE + d4*4) = acc;
            if (t == T-1)
                *(float4*)(out + OFF_CTXF + b*DE + d4*4) = acc;
        }
        __syncthreads();
    }

    // ---- copy_gate = sigmoid([h_new, new_ctx] @ W_copy + b_copy) ----
    {
        float g = sh[tid] * W_copy[tid] + sctx[tid] * W_copy[DM + tid];
        float gs = bsum(g, sred, tid);
        if (tid == 0)
            out[OFF_GATE + b*T + t] = sigmoid_fast(gs + b_copy[0]);
    }
}

// ---------------- launch ------------------------------------------------------

static cudaStream_t g_s2 = 0;
static cudaEvent_t  g_evF = 0, g_evJ = 0;

extern "C" void kernel_launch(void* const* d_in, const int* in_sizes, int n_in,
                              void* d_out, int out_size)
{
    const int*   tgt      = (const int*)  d_in[0];
    const int*   src      = (const int*)  d_in[1];
    const float* enc      = (const float*)d_in[2];
    const float* hidden   = (const float*)d_in[3];
    const float* word_emb = (const float*)d_in[4];
    const float* W_init   = (const float*)d_in[5];
    const float* b_init   = (const float*)d_in[6];
    const float* Wx       = (const float*)d_in[7];
    const float* Wh       = (const float*)d_in[8];
    const float* bx       = (const float*)d_in[9];
    const float* bh       = (const float*)d_in[10];
    const float* Wc       = (const float*)d_in[11];
    const float* Wq       = (const float*)d_in[12];
    const float* w_cov    = (const float*)d_in[13];
    const float* v_att    = (const float*)d_in[14];
    const float* W_copy   = (const float*)d_in[15];
    const float* b_copy   = (const float*)d_in[16];
    const float* W_read   = (const float*)d_in[17];
    const float* b_read   = (const float*)d_in[18];
    float* out = (float*)d_out;

    if (!g_s2) {   // one-time host-side resource init (no device memory)
        cudaStreamCreateWithFlags(&g_s2, cudaStreamNonBlocking);
        cudaEventCreateWithFlags(&g_evF, cudaEventDisableTiming);
        cudaEventCreateWithFlags(&g_evJ, cudaEventDisableTiming);
    }

    k_embed<<<T*B, 128>>>(tgt, word_emb);
    k_pre<<<(B*S)/16, dim3(16,16)>>>(enc, Wc);
    k_init<<<(B*DM)/256, 256>>>(hidden, W_init, b_init);

    for (int t = 0; t < T; t++) {
        k_big<<<576, dim3(8,16)>>>(t, Wx, Wh);
        k_attn<<<B, 512>>>(t, src, enc, Wq, w_cov, v_att, W_copy, b_copy,
                           bx, bh, out);
        // fork: readout for step t runs on g_s2, overlapped with step t+1
        cudaEventRecord(g_evF, 0);
        cudaStreamWaitEvent(g_s2, g_evF, 0);
        k_ro<<<192, dim3(8,16), 0, g_s2>>>(t, W_read);
        k_rored<<<B, 256, 0, g_s2>>>(t, b_read, out);
    }
    // join side stream back into the capture stream
    cudaEventRecord(g_evJ, g_s2);
    cudaStreamWaitEvent(0, g_evJ, 0);
}

// round 11
// speedup vs baseline: 1.5233x; 1.1604x over previous
#include <cuda_runtime.h>
#include <math.h>

#define B   32
#define T   64
#define S   400
#define DW  512
#define DM  512
#define DE  512
#define DK  64
#define G3  (3*DM)          // 1536
#define PAD_ID 50256

// ---------------- scratch (device globals) ------------------------------------
__device__ float g_emb[T*B*DW];       // [T,B,DW]
__device__ float g_pre[B*S*DK];       // enc @ Wc
__device__ float g_h  [B*DM];
__device__ float g_ctx[B*DE];
__device__ float g_cov[B*S];
__device__ float g_encw[B*S];         // enc @ W_copy[DM:] (one-time)
__device__ float g_gxp[8][B*G3];      // gx split-K partials
__device__ float g_ghp[4][B*G3];      // gh split-K partials
__device__ float g_rop[12][B*DM];     // readout split-K partials

// out layout (float32):
#define OFF_PRED      0
#define OFF_ATTNLAST  524288
#define OFF_CTXF      537088
#define OFF_COPY      553472
#define OFF_GATE      1372672
#define OFF_COVP      1374720

__device__ __forceinline__ float tanh_fast(float x) {
    float y; asm("tanh.approx.f32 %0, %1;" : "=f"(y) : "f"(x)); return y;
}
__device__ __forceinline__ float sigmoid_fast(float x) {
    return 1.f / (1.f + __expf(-x));
}

// block reductions for 512 threads (16 warps), via shuffles. sred[16].
__device__ __forceinline__ float bsum(float v, float* sred, int tid) {
    __syncthreads();
#pragma unroll
    for (int o = 16; o > 0; o >>= 1) v += __shfl_xor_sync(~0u, v, o);
    if ((tid & 31) == 0) sred[tid >> 5] = v;
    __syncthreads();
    if (tid < 32) {
        float x = (tid < 16) ? sred[tid] : 0.f;
#pragma unroll
        for (int o = 8; o > 0; o >>= 1) x += __shfl_xor_sync(~0u, x, o);
        if (tid == 0) sred[0] = x;
    }
    __syncthreads();
    return sred[0];
}
__device__ __forceinline__ float bmax(float v, float* sred, int tid) {
    __syncthreads();
#pragma unroll
    for (int o = 16; o > 0; o >>= 1) v = fmaxf(v, __shfl_xor_sync(~0u, v, o));
    if ((tid & 31) == 0) sred[tid >> 5] = v;
    __syncthreads();
    if (tid < 32) {
        float x = (tid < 16) ? sred[tid] : -1e30f;
#pragma unroll
        for (int o = 8; o > 0; o >>= 1) x = fmaxf(x, __shfl_xor_sync(~0u, x, o));
        if (tid == 0) sred[0] = x;
    }
    __syncthreads();
    return sred[0];
}

// ---------------- one-time kernels -------------------------------------------

__global__ void k_embed(const int* __restrict__ tgt, const float* __restrict__ word_emb)
{
    int row = blockIdx.x;                 // row = t*B + b
    int t = row / B, b = row % B;
    int id = tgt[b*T + t];
    const float4* src = (const float4*)(word_emb + (long long)id * DW);
    float4* dst = (float4*)(g_emb + (long long)row * DW);
    dst[threadIdx.x] = src[threadIdx.x];
}

__global__ void k_pre(const float* __restrict__ enc, const float* __restrict__ Wc)
{
    int row = blockIdx.x * 16 + threadIdx.y;        // grid 800, block (16,16)
    int n   = threadIdx.x * 4;
    const float* a = enc + (long long)row * DE;
    float4 acc = make_float4(0.f,0.f,0.f,0.f);
#pragma unroll 8
    for (int k = 0; k < DE; k++) {
        float av = a[k];
        float4 wv = *(const float4*)(Wc + k*DK + n);
        acc.x = fmaf(av, wv.x, acc.x); acc.y = fmaf(av, wv.y, acc.y);
        acc.z = fmaf(av, wv.z, acc.z); acc.w = fmaf(av, wv.w, acc.w);
    }
    *(float4*)(g_pre + (long long)row*DK + n) = acc;
}

// encw[row] = enc[row,:] . W_copy[DM:]  (one warp per row; grid B*S/8, block 256)
__global__ void k_encw(const float* __restrict__ enc, const float* __restrict__ W_copy)
{
    int row  = blockIdx.x * 8 + (threadIdx.x >> 5);
    int lane = threadIdx.x & 31;
    const float* e = enc + (size_t)row * DE;
    float acc = 0.f;
#pragma unroll 4
    for (int k = lane; k < DE; k += 32)
        acc = fmaf(e[k], W_copy[DM + k], acc);
#pragma unroll
    for (int o = 16; o > 0; o >>= 1) acc += __shfl_xor_sync(~0u, acc, o);
    if (lane == 0) g_encw[row] = acc;
}

__global__ void k_init(const float* __restrict__ hidden,
                       const float* __restrict__ W_init,
                       const float* __restrict__ b_init)
{
    int idx = blockIdx.x * 256 + threadIdx.x;   // 0..16383
    int b = idx / DM, j = idx % DM;
    const float* a = hidden + b * DE;
    float acc = b_init[j];
#pragma unroll 8
    for (int k = 0; k < DE; k++)
        acc = fmaf(a[k], W_init[k*DM + j], acc);
    g_h[idx]   = tanhf(acc);
    g_ctx[idx] = 0.f;
    if (idx < B*S) g_cov[idx] = 0.f;
}

// ---------------- per-step GEMM kernel (768 blocks, R6 config) ----------------
// block (8,16) = 128 thr: tx -> 4 n-cols, ty -> 2 batch rows. K-chunk 128.
// bid [0,384):   gx  48 n-tiles x 8 k-chunks  (Wx, K=1024)
// bid [384,576): gh  48 n-tiles x 4 k-chunks  (Wh, K=512)
// bid [576,768): ro  16 n-tiles x 12 k-chunks (W_read, K=1536) for step t-1
__global__ void k_big(int t,
                      const float* __restrict__ Wx, const float* __restrict__ Wh,
                      const float* __restrict__ W_read)
{
    __shared__ float sAct[32][132];

    int bid = blockIdx.x;
    int tx = threadIdx.x;      // 0..7
    int ty = threadIdx.y;      // 0..15
    int tid = ty*8 + tx;

    const float* W; int n0, k0, stride, ks, mode;
    if (bid < 384) {
        if (t >= T) return;
        mode = 0; ks = bid & 7; n0 = (bid >> 3) * 32; k0 = ks * 128;
        W = Wx; stride = G3;
    } else if (bid < 576) {
        if (t >= T) return;
        int r = bid - 384;
        mode = 1; ks = r & 3; n0 = (r >> 2) * 32; k0 = ks * 128;
        W = Wh; stride = G3;
    } else {
        if (t == 0) return;
        int r = bid - 576;
        mode = 2; ks = r % 12; n0 = (r / 12) * 32; k0 = ks * 128;
        W = W_read; stride = DM;
    }

    // cooperative load of act chunk [32][128]
#pragma unroll
    for (int j = 0; j < 8; j++) {
        int f   = tid + j * 128;
        int row = f >> 5;
        int col = (f & 31) * 4;
        int kg  = k0 + col;
        const float* src;
        if (mode == 0) {
            src = (kg < 512) ? g_emb + ((size_t)t*B + row)*DW + kg
                             : g_ctx + row*DE + (kg - 512);
        } else if (mode == 1) {
            src = g_h + row*DM + kg;
        } else {
            if (kg < 512)       src = g_emb + ((size_t)(t-1)*B + row)*DW + kg;
            else if (kg < 1024) src = g_h   + row*DM + (kg - 512);
            else                src = g_ctx + row*DE + (kg - 1024);
        }
        *(float4*)&sAct[row][col] = *(const float4*)src;
    }
    __syncthreads();

    int n  = n0 + tx * 4;
    int b0 = ty * 2;
    const float* wp = W + (size_t)k0 * stride + n;
    float4 a0 = make_float4(0.f,0.f,0.f,0.f);
    float4 a1 = make_float4(0.f,0.f,0.f,0.f);

#pragma unroll 4
    for (int k = 0; k < 128; k += 4) {
        float4 x0 = *(const float4*)&sAct[b0][k];
        float4 x1 = *(const float4*)&sAct[b0+1][k];
        float4 w0 = *(const float4*)(wp + (size_t)(k  ) * stride);
        float4 w1 = *(const float4*)(wp + (size_t)(k+1) * stride);
        float4 w2 = *(const float4*)(wp + (size_t)(k+2) * stride);
        float4 w3 = *(const float4*)(wp + (size_t)(k+3) * stride);
        a0.x = fmaf(x0.x,w0.x,a0.x); a0.y = fmaf(x0.x,w0.y,a0.y);
        a0.z = fmaf(x0.x,w0.z,a0.z); a0.w = fmaf(x0.x,w0.w,a0.w);
        a1.x = fmaf(x1.x,w0.x,a1.x); a1.y = fmaf(x1.x,w0.y,a1.y);
        a1.z = fmaf(x1.x,w0.z,a1.z); a1.w = fmaf(x1.x,w0.w,a1.w);
        a0.x = fmaf(x0.y,w1.x,a0.x); a0.y = fmaf(x0.y,w1.y,a0.y);
        a0.z = fmaf(x0.y,w1.z,a0.z); a0.w = fmaf(x0.y,w1.w,a0.w);
        a1.x = fmaf(x1.y,w1.x,a1.x); a1.y = fmaf(x1.y,w1.y,a1.y);
        a1.z = fmaf(x1.y,w1.z,a1.z); a1.w = fmaf(x1.y,w1.w,a1.w);
        a0.x = fmaf(x0.z,w2.x,a0.x); a0.y = fmaf(x0.z,w2.y,a0.y);
        a0.z = fmaf(x0.z,w2.z,a0.z); a0.w = fmaf(x0.z,w2.w,a0.w);
        a1.x = fmaf(x1.z,w2.x,a1.x); a1.y = fmaf(x1.z,w2.y,a1.y);
        a1.z = fmaf(x1.z,w2.z,a1.z); a1.w = fmaf(x1.z,w2.w,a1.w);
        a0.x = fmaf(x0.w,w3.x,a0.x); a0.y = fmaf(x0.w,w3.y,a0.y);
        a0.z = fmaf(x0.w,w3.z,a0.z); a0.w = fmaf(x0.w,w3.w,a0.w);
        a1.x = fmaf(x1.w,w3.x,a1.x); a1.y = fmaf(x1.w,w3.y,a1.y);
        a1.z = fmaf(x1.w,w3.z,a1.z); a1.w = fmaf(x1.w,w3.w,a1.w);
    }

    if (mode == 0) {
        *(float4*)(g_gxp[ks] + (size_t)b0*G3 + n)     = a0;
        *(float4*)(g_gxp[ks] + (size_t)(b0+1)*G3 + n) = a1;
    } else if (mode == 1) {
        *(float4*)(g_ghp[ks] + (size_t)b0*G3 + n)     = a0;
        *(float4*)(g_ghp[ks] + (size_t)(b0+1)*G3 + n) = a1;
    } else {
        *(float4*)(g_rop[ks] + (size_t)b0*DM + n)     = a0;
        *(float4*)(g_rop[ks] + (size_t)(b0+1)*DM + n) = a1;
    }
}

// ---------------- per-step attention kernel (32 blocks x 512 thr) -------------
// GRU gates, q, scores, softmax, coverage, copy_gate (via encw). NO ctx GEMV.
__global__ void k_attn(int t,
                       const int*   __restrict__ src_seq,
                       const float* __restrict__ Wq,
                       const float* __restrict__ w_cov,
                       const float* __restrict__ v_att,
                       const float* __restrict__ W_copy,
                       const float* __restrict__ b_copy,
                       const float* __restrict__ bx,
                       const float* __restrict__ bh,
                       const float* __restrict__ b_read,
                       float* __restrict__ out)
{
    int b   = blockIdx.x;
    int tid = threadIdx.x;                 // 0..511

    __shared__ float sh[DM];
    __shared__ float sq[DK];
    __shared__ float sqp[8][DK];
    __shared__ float swc[DK];
    __shared__ float sva[DK];
    __shared__ float ss[S];
    __shared__ float sred[16];

    // ---- readout reduce + maxout for step t-1 (independent side phase) ----
    if (t > 0 && tid < 256) {
        float2 acc = *(const float2*)(b_read + tid*2);
#pragma unroll
        for (int p = 0; p < 12; p++) {
            float2 v = *(const float2*)(g_rop[p] + (size_t)b*DM + tid*2);
            acc.x += v.x; acc.y += v.y;
        }
        out[OFF_PRED + ((size_t)b*T + (t-1)) * (DM/2) + tid] = fmaxf(acc.x, acc.y);
    }

    // ---- GRU gates -> h_new ----
    {
        int j = tid;
        size_t base = (size_t)b*G3 + j;
        float gxr = bx[j],        ghr = bh[j];
        float gxz = bx[DM+j],     ghz = bh[DM+j];
        float gxn = bx[2*DM+j],   ghn = bh[2*DM+j];
#pragma unroll
        for (int p = 0; p < 8; p++) {
            gxr += g_gxp[p][base];
            gxz += g_gxp[p][base + DM];
            gxn += g_gxp[p][base + 2*DM];
        }
#pragma unroll
        for (int p = 0; p < 4; p++) {
            ghr += g_ghp[p][base];
            ghz += g_ghp[p][base + DM];
            ghn += g_ghp[p][base + 2*DM];
        }
        float r  = sigmoid_fast(gxr + ghr);
        float z  = sigmoid_fast(gxz + ghz);
        float nn = tanh_fast(gxn + r * ghn);
        float ho = g_h[b*DM + j];
        float hn = (1.f - z) * nn + z * ho;
        sh[j] = hn;
        g_h[b*DM + j] = hn;
    }
    __syncthreads();

    // ---- q = h_new @ Wq  (split-K over 8 parts of 64) ----
    {
        int j = tid & 63, p = tid >> 6;     // p 0..7
        float acc = 0.f;
#pragma unroll 8
        for (int k = p*64; k < (p+1)*64; k++)
            acc = fmaf(sh[k], Wq[k*DK + j], acc);
        sqp[p][j] = acc;
        if (tid < DK)          swc[tid]      = w_cov[tid];
        else if (tid < 2*DK)   sva[tid - DK] = v_att[tid - DK];
    }
    __syncthreads();
    if (tid < DK) {
        float s = 0.f;
#pragma unroll
        for (int p = 0; p < 8; p++) s += sqp[p][tid];
        sq[tid] = s;
    }
    __syncthreads();

    // ---- attention scores with coverage + pad mask ----
    float cv = 0.f;
    if (tid < S) {
        cv = g_cov[b*S + tid];
        const float4* pr = (const float4*)(g_pre + ((size_t)b*S + tid) * DK);
        float acc = 0.f;
#pragma unroll
        for (int k4 = 0; k4 < 16; k4++) {
            float4 p = pr[k4];
            int k = k4*4;
            acc = fmaf(tanh_fast(p.x + sq[k  ] + cv*swc[k  ]), sva[k  ], acc);
            acc = fmaf(tanh_fast(p.y + sq[k+1] + cv*swc[k+1]), sva[k+1], acc);
            acc = fmaf(tanh_fast(p.z + sq[k+2] + cv*swc[k+2]), sva[k+2], acc);
            acc = fmaf(tanh_fast(p.w + sq[k+3] + cv*swc[k+3]), sva[k+3], acc);
        }
        if (src_seq[b*S + tid] == PAD_ID) acc = -1e9f;
        ss[tid] = acc;
    }

    // ---- softmax over S ----
    float m = bmax((tid < S) ? ss[tid] : -1e30f, sred, tid);
    float e = 0.f;
    if (tid < S) { e = __expf(ss[tid] - m); }
    float inv = 1.f / bsum(e, sred, tid);

    // ---- attn, coverage update, outputs ----
    float cl = 0.f;
    float tden = fmaxf((float)t, 1.f);
    if (tid < S) {
        float a = e * inv; ss[tid] = a;
        cl = fminf(a, cv / tden);
        g_cov[b*S + tid] = cv + a;
        out[OFF_COPY + (size_t)b*T*S + (size_t)t*S + tid] = a;
        if (t == T-1) out[OFF_ATTNLAST + b*S + tid] = a;
    }
    float clsum = bsum(cl, sred, tid);
    if (tid == 0) out[OFF_COVP + b*T + t] = clsum;

    // ---- copy_gate = sigmoid(h.W1 + attn.encw + b)  (ctx part reassociated) --
    {
        float g = sh[tid] * W_copy[tid];
        if (tid < S) g = fmaf(ss[tid], g_encw[b*S + tid], g);
        float gs = bsum(g, sred, tid);
        if (tid == 0)
            out[OFF_GATE + b*T + t] = sigmoid_fast(gs + b_copy[0]);
    }
}

// ---------------- ctx GEMV, full-chip (256 blocks x 256 thr) ------------------
// block = (b, q): b = bid>>3, q = bid&7 owns 64 floats (16 float4) of DE.
// ctx[b, q-slice] = sum_s attn[b,s] * enc[b,s,q-slice]
__global__ void k_ctx(int t, const float* __restrict__ enc, float* __restrict__ out)
{
    int b  = blockIdx.x >> 3;
    int q  = blockIdx.x & 7;
    int tid = threadIdx.x;       // 0..255
    int sg = tid >> 4;           // s-group 0..15
    int c4 = tid & 15;           // float4 col in slice
    int d4 = q*16 + c4;          // global float4 col 0..127

    __shared__ float sa[S];
    __shared__ float4 part[16][17];

    for (int s = tid; s < S; s += 256)
        sa[s] = out[OFF_COPY + (size_t)b*T*S + (size_t)t*S + s];
    __syncthreads();

    const float4* e4 = (const float4*)(enc + (size_t)b*S*DE);
    float4 acc = make_float4(0.f,0.f,0.f,0.f);
    int s0 = sg * 25;
#pragma unroll 5
    for (int i = 0; i < 25; i++) {
        int s = s0 + i;
        float a = sa[s];
        float4 v = e4[(size_t)s*(DE/4) + d4];
        acc.x = fmaf(a,v.x,acc.x); acc.y = fmaf(a,v.y,acc.y);
        acc.z = fmaf(a,v.z,acc.z); acc.w = fmaf(a,v.w,acc.w);
    }
    part[sg][c4] = acc;
    __syncthreads();
#pragma unroll
    for (int st = 8; st > 0; st >>= 1) {
        if (sg < st) {
            float4 o = part[sg+st][c4];
            acc.x += o.x; acc.y += o.y; acc.z += o.z; acc.w += o.w;
            part[sg][c4] = acc;
        }
        __syncthreads();
    }
    if (sg == 0) {
        *(float4*)(g_ctx + b*DE + d4*4) = acc;
        if (t == T-1)
            *(float4*)(out + OFF_CTXF + b*DE + d4*4) = acc;
    }
}

// final readout reduce for t = T-1
__global__ void k_rofin(const float* __restrict__ b_read, float* __restrict__ out)
{
    int b = blockIdx.x, tid = threadIdx.x;   // 32 blocks x 256
    float2 acc = *(const float2*)(b_read + tid*2);
#pragma unroll
    for (int p = 0; p < 12; p++) {
        float2 v = *(const float2*)(g_rop[p] + (size_t)b*DM + tid*2);
        acc.x += v.x; acc.y += v.y;
    }
    out[OFF_PRED + ((size_t)b*T + (T-1)) * (DM/2) + tid] = fmaxf(acc.x, acc.y);
}

// ---------------- launch ------------------------------------------------------

extern "C" void kernel_launch(void* const* d_in, const int* in_sizes, int n_in,
                              void* d_out, int out_size)
{
    const int*   tgt      = (const int*)  d_in[0];
    const int*   src      = (const int*)  d_in[1];
    const float* enc      = (const float*)d_in[2];
    const float* hidden   = (const float*)d_in[3];
    const float* word_emb = (const float*)d_in[4];
    const float* W_init   = (const float*)d_in[5];
    const float* b_init   = (const float*)d_in[6];
    const float* Wx       = (const float*)d_in[7];
    const float* Wh       = (const float*)d_in[8];
    const float* bx       = (const float*)d_in[9];
    const float* bh       = (const float*)d_in[10];
    const float* Wc       = (const float*)d_in[11];
    const float* Wq       = (const float*)d_in[12];
    const float* w_cov    = (const float*)d_in[13];
    const float* v_att    = (const float*)d_in[14];
    const float* W_copy   = (const float*)d_in[15];
    const float* b_copy   = (const float*)d_in[16];
    const float* W_read   = (const float*)d_in[17];
    const float* b_read   = (const float*)d_in[18];
    float* out = (float*)d_out;

    k_embed<<<T*B, 128>>>(tgt, word_emb);
    k_pre<<<(B*S)/16, dim3(16,16)>>>(enc, Wc);
    k_encw<<<(B*S)/8, 256>>>(enc, W_copy);
    k_init<<<(B*DM)/256, 256>>>(hidden, W_init, b_init);

    for (int t = 0; t < T; t++) {
        k_big<<<768, dim3(8,16)>>>(t, Wx, Wh, W_read);
        k_attn<<<B, 512>>>(t, src, Wq, w_cov, v_att, W_copy, b_copy,
                           bx, bh, b_read, out);
        k_ctx<<<B*8, 256>>>(t, enc, out);
    }
    k_big<<<768, dim3(8,16)>>>(T, Wx, Wh, W_read);   // readout for t=T-1
    k_rofin<<<B, 256>>>(b_read, out);
}

// round 12
// speedup vs baseline: 1.6126x; 1.0586x over previous
#include <cuda_runtime.h>
#include <math.h>

#define B   32
#define T   64
#define S   400
#define DW  512
#define DM  512
#define DE  512
#define DK  64
#define G3  (3*DM)          // 1536
#define BDM (B*DM)          // 16384
#define PAD_ID 50256
#define NBLK 296

// ---------------- scratch (device globals) ------------------------------------
__device__ float g_emb[T*B*DW];
__device__ float g_pre[B*S*DK];
__device__ float g_encw[B*S];
__device__ float g_cov[B*S];
__device__ float g_hbuf[2][BDM];      // h ping-pong: h[t] at slot t&1
__device__ float g_cbuf[2][BDM];      // ctx ping-pong: ctx[t] at slot t&1
__device__ float g_gxp[8][B*G3];
__device__ float g_ghp[4][B*G3];
__device__ float g_rop[12][BDM];
__device__ unsigned g_barcnt;

#define OFF_PRED      0
#define OFF_ATTNLAST  524288
#define OFF_CTXF      537088
#define OFF_COPY      553472
#define OFF_GATE      1372672
#define OFF_COVP      1374720

__device__ __forceinline__ float tanh_fast(float x) {
    float y; asm("tanh.approx.f32 %0, %1;" : "=f"(y) : "f"(x)); return y;
}
__device__ __forceinline__ float sigmoid_fast(float x) {
    return 1.f / (1.f + __expf(-x));
}

// grid-wide barrier: all NBLK blocks co-resident (exact-fit persistent grid)
__device__ __forceinline__ void gbar(unsigned target) {
    __syncthreads();
    if (threadIdx.x == 0) {
        __threadfence();
        atomicAdd(&g_barcnt, 1u);
        volatile unsigned* p = &g_barcnt;
        while (*p < target) __nanosleep(64);
        __threadfence();
    }
    __syncthreads();
}

// 256-thread block reductions (8 warps), sred[8]
__device__ __forceinline__ float bsum256(float v, float* sred) {
    int tid = threadIdx.x;
    __syncthreads();
#pragma unroll
    for (int o = 16; o > 0; o >>= 1) v += __shfl_xor_sync(~0u, v, o);
    if ((tid & 31) == 0) sred[tid >> 5] = v;
    __syncthreads();
    if (tid < 32) {
        float x = (tid < 8) ? sred[tid] : 0.f;
#pragma unroll
        for (int o = 4; o > 0; o >>= 1) x += __shfl_xor_sync(~0u, x, o);
        if (tid == 0) sred[0] = x;
    }
    __syncthreads();
    return sred[0];
}
__device__ __forceinline__ float bmax256(float v, float* sred) {
    int tid = threadIdx.x;
    __syncthreads();
#pragma unroll
    for (int o = 16; o > 0; o >>= 1) v = fmaxf(v, __shfl_xor_sync(~0u, v, o));
    if ((tid & 31) == 0) sred[tid >> 5] = v;
    __syncthreads();
    if (tid < 32) {
        float x = (tid < 8) ? sred[tid] : -1e30f;
#pragma unroll
        for (int o = 4; o > 0; o >>= 1) x = fmaxf(x, __shfl_xor_sync(~0u, x, o));
        if (tid == 0) sred[0] = x;
    }
    __syncthreads();
    return sred[0];
}

// ---------------- one-time kernels -------------------------------------------

__global__ void k_embed(const int* __restrict__ tgt, const float* __restrict__ word_emb)
{
    int row = blockIdx.x;
    int t = row / B, b = row % B;
    int id = tgt[b*T + t];
    const float4* src = (const float4*)(word_emb + (long long)id * DW);
    float4* dst = (float4*)(g_emb + (long long)row * DW);
    dst[threadIdx.x] = src[threadIdx.x];
}

__global__ void k_pre(const float* __restrict__ enc, const float* __restrict__ Wc)
{
    int row = blockIdx.x * 16 + threadIdx.y;
    int n   = threadIdx.x * 4;
    const float* a = enc + (long long)row * DE;
    float4 acc = make_float4(0.f,0.f,0.f,0.f);
#pragma unroll 8
    for (int k = 0; k < DE; k++) {
        float av = a[k];
        float4 wv = *(const float4*)(Wc + k*DK + n);
        acc.x = fmaf(av, wv.x, acc.x); acc.y = fmaf(av, wv.y, acc.y);
        acc.z = fmaf(av, wv.z, acc.z); acc.w = fmaf(av, wv.w, acc.w);
    }
    *(float4*)(g_pre + (long long)row*DK + n) = acc;
}

__global__ void k_encw(const float* __restrict__ enc, const float* __restrict__ W_copy)
{
    int row  = blockIdx.x * 8 + (threadIdx.x >> 5);
    int lane = threadIdx.x & 31;
    const float* e = enc + (size_t)row * DE;
    float acc = 0.f;
#pragma unroll 4
    for (int k = lane; k < DE; k += 32)
        acc = fmaf(e[k], W_copy[DM + k], acc);
#pragma unroll
    for (int o = 16; o > 0; o >>= 1) acc += __shfl_xor_sync(~0u, acc, o);
    if (lane == 0) g_encw[row] = acc;
}

// reset mutable state (every replay): ctx[0]=0, cov=0, barrier=0
__global__ void k_init0()
{
    int idx = blockIdx.x * 256 + threadIdx.x;   // 64 blocks -> 0..16383
    g_cbuf[0][idx] = 0.f;
    if (idx < B*S) g_cov[idx] = 0.f;
    if (idx == 0)  g_barcnt = 0u;
}

// ---------------- persistent-kernel phase bodies ------------------------------

// gemm tile: 128-thread unit. mode 0=gx 1=gh 2=readout(step tt)
__device__ __forceinline__ void gemm_tile(
    int mode, int tt, int ks, int n0, int utid,
    const float* __restrict__ Wx, const float* __restrict__ Wh,
    const float* __restrict__ W_read, float* sA /* 32x132 */)
{
    const float* W; int stride;
    int k0 = ks * 128;
    if (mode == 0)      { W = Wx;     stride = G3; }
    else if (mode == 1) { W = Wh;     stride = G3; }
    else                { W = W_read; stride = DM; }
    int hs = (mode == 2) ? ((tt+1)&1) : (tt&1);

#pragma unroll
    for (int j = 0; j < 8; j++) {
        int f = utid + j*128;
        int row = f >> 5;
        int col = (f & 31) * 4;
        int kg = k0 + col;
        const float* src;
        if (mode == 0) {
            src = (kg < 512) ? g_emb + ((size_t)tt*B + row)*DW + kg
                             : g_cbuf[tt&1] + row*DE + (kg - 512);
        } else if (mode == 1) {
            src = g_hbuf[tt&1] + row*DM + kg;
        } else {
            if (kg < 512)       src = g_emb + ((size_t)tt*B + row)*DW + kg;
            else if (kg < 1024) src = g_hbuf[hs] + row*DM + (kg - 512);
            else                src = g_cbuf[hs] + row*DE + (kg - 1024);
        }
        *(float4*)&sA[row*132 + col] = __ldcg((const float4*)src);
    }
    __syncthreads();

    int tx = utid & 7, ty = utid >> 3;
    int n  = n0 + tx * 4;
    int b0 = ty * 2;
    const float* wp = W + (size_t)k0 * stride + n;
    float4 a0 = make_float4(0.f,0.f,0.f,0.f);
    float4 a1 = make_float4(0.f,0.f,0.f,0.f);

#pragma unroll 4
    for (int k = 0; k < 128; k += 4) {
        float4 x0 = *(const float4*)&sA[b0*132 + k];
        float4 x1 = *(const float4*)&sA[(b0+1)*132 + k];
        float4 w0 = *(const float4*)(wp + (size_t)(k  ) * stride);
        float4 w1 = *(const float4*)(wp + (size_t)(k+1) * stride);
        float4 w2 = *(const float4*)(wp + (size_t)(k+2) * stride);
        float4 w3 = *(const float4*)(wp + (size_t)(k+3) * stride);
        a0.x = fmaf(x0.x,w0.x,a0.x); a0.y = fmaf(x0.x,w0.y,a0.y);
        a0.z = fmaf(x0.x,w0.z,a0.z); a0.w = fmaf(x0.x,w0.w,a0.w);
        a1.x = fmaf(x1.x,w0.x,a1.x); a1.y = fmaf(x1.x,w0.y,a1.y);
        a1.z = fmaf(x1.x,w0.z,a1.z); a1.w = fmaf(x1.x,w0.w,a1.w);
        a0.x = fmaf(x0.y,w1.x,a0.x); a0.y = fmaf(x0.y,w1.y,a0.y);
        a0.z = fmaf(x0.y,w1.z,a0.z); a0.w = fmaf(x0.y,w1.w,a0.w);
        a1.x = fmaf(x1.y,w1.x,a1.x); a1.y = fmaf(x1.y,w1.y,a1.y);
        a1.z = fmaf(x1.y,w1.z,a1.z); a1.w = fmaf(x1.y,w1.w,a1.w);
        a0.x = fmaf(x0.z,w2.x,a0.x); a0.y = fmaf(x0.z,w2.y,a0.y);
        a0.z = fmaf(x0.z,w2.z,a0.z); a0.w = fmaf(x0.z,w2.w,a0.w);
        a1.x = fmaf(x1.z,w2.x,a1.x); a1.y = fmaf(x1.z,w2.y,a1.y);
        a1.z = fmaf(x1.z,w2.z,a1.z); a1.w = fmaf(x1.z,w2.w,a1.w);
        a0.x = fmaf(x0.w,w3.x,a0.x); a0.y = fmaf(x0.w,w3.y,a0.y);
        a0.z = fmaf(x0.w,w3.z,a0.z); a0.w = fmaf(x0.w,w3.w,a0.w);
        a1.x = fmaf(x1.w,w3.x,a1.x); a1.y = fmaf(x1.w,w3.y,a1.y);
        a1.z = fmaf(x1.w,w3.z,a1.z); a1.w = fmaf(x1.w,w3.w,a1.w);
    }

    if (mode == 0) {
        __stcg((float4*)(g_gxp[ks] + (size_t)b0*G3 + n),     a0);
        __stcg((float4*)(g_gxp[ks] + (size_t)(b0+1)*G3 + n), a1);
    } else if (mode == 1) {
        __stcg((float4*)(g_ghp[ks] + (size_t)b0*G3 + n),     a0);
        __stcg((float4*)(g_ghp[ks] + (size_t)(b0+1)*G3 + n), a1);
    } else {
        __stcg((float4*)(g_rop[ks] + (size_t)b0*DM + n),     a0);
        __stcg((float4*)(g_rop[ks] + (size_t)(b0+1)*DM + n), a1);
    }
}

// attn for batch row b, 256 threads
__device__ void attn_task(int t, int b,
    const int* __restrict__ src_seq,
    const float* __restrict__ Wq, const float* __restrict__ w_cov,
    const float* __restrict__ v_att, const float* __restrict__ W_copy,
    const float* __restrict__ b_copy, const float* __restrict__ bx,
    const float* __restrict__ bh, float* __restrict__ out, float* sm)
{
    int tid = threadIdx.x;
    float* sh   = sm;          // 512
    float* sq   = sm + 512;    // 64
    float* sqp  = sm + 576;    // 256
    float* swc  = sm + 832;    // 64
    float* sva  = sm + 896;    // 64
    float* ss   = sm + 960;    // 400
    float* sred = sm + 1368;   // 8

    // GRU gates (2 j's per thread)
#pragma unroll
    for (int jj = 0; jj < 2; jj++) {
        int j = tid + jj*256;
        size_t base = (size_t)b*G3 + j;
        float gxr = bx[j],      ghr = bh[j];
        float gxz = bx[DM+j],   ghz = bh[DM+j];
        float gxn = bx[2*DM+j], ghn = bh[2*DM+j];
#pragma unroll
        for (int p = 0; p < 8; p++) {
            gxr += __ldcg(&g_gxp[p][base]);
            gxz += __ldcg(&g_gxp[p][base + DM]);
            gxn += __ldcg(&g_gxp[p][base + 2*DM]);
        }
#pragma unroll
        for (int p = 0; p < 4; p++) {
            ghr += __ldcg(&g_ghp[p][base]);
            ghz += __ldcg(&g_ghp[p][base + DM]);
            ghn += __ldcg(&g_ghp[p][base + 2*DM]);
        }
        float r  = sigmoid_fast(gxr + ghr);
        float z  = sigmoid_fast(gxz + ghz);
        float nn = tanh_fast(gxn + r * ghn);
        float ho = __ldcg(&g_hbuf[t&1][b*DM + j]);
        float hn = (1.f - z) * nn + z * ho;
        sh[j] = hn;
        __stcg(&g_hbuf[(t+1)&1][b*DM + j], hn);
    }
    __syncthreads();

    // q = h @ Wq, split-K 4x128
    {
        int j = tid & 63, p = tid >> 6;
        float acc = 0.f;
#pragma unroll 8
        for (int k = p*128; k < (p+1)*128; k++)
            acc = fmaf(sh[k], Wq[k*DK + j], acc);
        sqp[p*64 + j] = acc;
        if (tid < 64)        swc[tid]      = w_cov[tid];
        else if (tid < 128)  sva[tid - 64] = v_att[tid - 64];
    }
    __syncthreads();
    if (tid < 64) sq[tid] = sqp[tid] + sqp[64+tid] + sqp[128+tid] + sqp[192+tid];
    __syncthreads();

    // scores at s0 = tid (always valid), s1 = tid+256 (valid if < S)
    int s0 = tid, s1 = tid + 256;
    float cv0 = g_cov[b*S + s0];
    float cv1 = (s1 < S) ? g_cov[b*S + s1] : 0.f;
    {
        const float4* pr = (const float4*)(g_pre + ((size_t)b*S + s0) * DK);
        float acc = 0.f;
#pragma unroll
        for (int k4 = 0; k4 < 16; k4++) {
            float4 p = pr[k4]; int k = k4*4;
            acc = fmaf(tanh_fast(p.x + sq[k  ] + cv0*swc[k  ]), sva[k  ], acc);
            acc = fmaf(tanh_fast(p.y + sq[k+1] + cv0*swc[k+1]), sva[k+1], acc);
            acc = fmaf(tanh_fast(p.z + sq[k+2] + cv0*swc[k+2]), sva[k+2], acc);
            acc = fmaf(tanh_fast(p.w + sq[k+3] + cv0*swc[k+3]), sva[k+3], acc);
        }
        if (src_seq[b*S + s0] == PAD_ID) acc = -1e9f;
        ss[s0] = acc;
    }
    if (s1 < S) {
        const float4* pr = (const float4*)(g_pre + ((size_t)b*S + s1) * DK);
        float acc = 0.f;
#pragma unroll
        for (int k4 = 0; k4 < 16; k4++) {
            float4 p = pr[k4]; int k = k4*4;
            acc = fmaf(tanh_fast(p.x + sq[k  ] + cv1*swc[k  ]), sva[k  ], acc);
            acc = fmaf(tanh_fast(p.y + sq[k+1] + cv1*swc[k+1]), sva[k+1], acc);
            acc = fmaf(tanh_fast(p.z + sq[k+2] + cv1*swc[k+2]), sva[k+2], acc);
            acc = fmaf(tanh_fast(p.w + sq[k+3] + cv1*swc[k+3]), sva[k+3], acc);
        }
        if (src_seq[b*S + s1] == PAD_ID) acc = -1e9f;
        ss[s1] = acc;
    }

    float m = bmax256(fmaxf(ss[s0], (s1 < S) ? ss[s1] : -1e30f), sred);
    float e0 = __expf(ss[s0] - m);
    float e1 = (s1 < S) ? __expf(ss[s1] - m) : 0.f;
    float inv = 1.f / bsum256(e0 + e1, sred);

    float tden = fmaxf((float)t, 1.f);
    float cl = 0.f;
    float a0 = e0 * inv;
    cl += fminf(a0, cv0 / tden);
    g_cov[b*S + s0] = cv0 + a0;
    __stcg(&out[OFF_COPY + (size_t)b*T*S + (size_t)t*S + s0], a0);
    if (t == T-1) out[OFF_ATTNLAST + b*S + s0] = a0;
    float a1 = 0.f;
    if (s1 < S) {
        a1 = e1 * inv;
        cl += fminf(a1, cv1 / tden);
        g_cov[b*S + s1] = cv1 + a1;
        __stcg(&out[OFF_COPY + (size_t)b*T*S + (size_t)t*S + s1], a1);
        if (t == T-1) out[OFF_ATTNLAST + b*S + s1] = a1;
    }
    float clsum = bsum256(cl, sred);
    if (tid == 0) out[OFF_COVP + b*T + t] = clsum;

    // copy gate: h.W1 + attn.encw
    float g = sh[tid] * W_copy[tid] + sh[tid+256] * W_copy[tid+256];
    g = fmaf(a0, g_encw[b*S + s0], g);
    if (s1 < S) g = fmaf(a1, g_encw[b*S + s1], g);
    float gs = bsum256(g, sred);
    if (tid == 0) out[OFF_GATE + b*T + t] = sigmoid_fast(gs + b_copy[0]);
}

// ctx[t] for task = blockIdx (0..255): b = task>>3, q = task&7
__device__ void ctx_task(int t, int task, const float* __restrict__ enc,
                         float* __restrict__ out, float* sm)
{
    int b = task >> 3, q = task & 7;
    int tid = threadIdx.x;
    int sg = tid >> 4, c4 = tid & 15;
    int d4 = q*16 + c4;
    float*  sa   = sm;
    float4* part = (float4*)(sm + 512);   // [16][17]

    for (int s = tid; s < S; s += 256)
        sa[s] = __ldcg(&out[OFF_COPY + (size_t)b*T*S + (size_t)(t-1)*S + s]);
    __syncthreads();

    const float4* e4 = (const float4*)(enc + (size_t)b*S*DE);
    float4 acc = make_float4(0.f,0.f,0.f,0.f);
    int s0 = sg * 25;
#pragma unroll 5
    for (int i = 0; i < 25; i++) {
        int s = s0 + i;
        float a = sa[s];
        float4 v = e4[(size_t)s*(DE/4) + d4];
        acc.x = fmaf(a,v.x,acc.x); acc.y = fmaf(a,v.y,acc.y);
        acc.z = fmaf(a,v.z,acc.z); acc.w = fmaf(a,v.w,acc.w);
    }
    part[sg*17 + c4] = acc;
    __syncthreads();
#pragma unroll
    for (int st = 8; st > 0; st >>= 1) {
        if (sg < st) {
            float4 o = part[(sg+st)*17 + c4];
            acc.x += o.x; acc.y += o.y; acc.z += o.z; acc.w += o.w;
            part[sg*17 + c4] = acc;
        }
        __syncthreads();
    }
    if (sg == 0) {
        __stcg((float4*)(g_cbuf[t&1] + b*DE + d4*4), acc);
        if (t == T)
            *(float4*)(out + OFF_CTXF + b*DE + d4*4) = acc;
    }
}

__device__ void rored_task(int tr, int b, const float* __restrict__ b_read,
                           float* __restrict__ out)
{
    int tid = threadIdx.x;
    float2 acc = *(const float2*)(b_read + tid*2);
#pragma unroll
    for (int p = 0; p < 12; p++) {
        float2 v = __ldcg((const float2*)(g_rop[p] + (size_t)b*DM + tid*2));
        acc.x += v.x; acc.y += v.y;
    }
    out[OFF_PRED + ((size_t)b*T + tr) * (DM/2) + tid] = fmaxf(acc.x, acc.y);
}

// h0 = tanh(hidden @ W_init + b_init): blocks 0..255, 64 outputs/block
__device__ void h0_task(const float* __restrict__ hidden,
                        const float* __restrict__ W_init,
                        const float* __restrict__ b_init, float* sm)
{
    int tid = threadIdx.x;
    int o = blockIdx.x * 64 + (tid >> 2);
    int part = tid & 3;
    int bb = o >> 9, j = o & 511;
    float acc = 0.f;
#pragma unroll 8
    for (int k = part*128; k < part*128 + 128; k++)
        acc = fmaf(hidden[bb*DE + k], W_init[k*DM + j], acc);
    sm[tid] = acc;
    __syncthreads();
    if (part == 0) {
        float v = sm[tid] + sm[tid+1] + sm[tid+2] + sm[tid+3] + b_init[j];
        __stcg(&g_hbuf[0][o], tanhf(v));
    }
}

// ---------------- the persistent kernel ---------------------------------------
__global__ void __launch_bounds__(256, 2)
k_persist(const int* __restrict__ src_seq,
          const float* __restrict__ enc,
          const float* __restrict__ hidden,
          const float* __restrict__ W_init, const float* __restrict__ b_init,
          const float* __restrict__ Wx, const float* __restrict__ Wh,
          const float* __restrict__ bx, const float* __restrict__ bh,
          const float* __restrict__ Wq, const float* __restrict__ w_cov,
          const float* __restrict__ v_att,
          const float* __restrict__ W_copy, const float* __restrict__ b_copy,
          const float* __restrict__ W_read, const float* __restrict__ b_read,
          float* __restrict__ out)
{
    extern __shared__ float sm[];       // 2 * 32*132 floats = 33792 B
    int bid = blockIdx.x;
    int tid = threadIdx.x;
    int half = tid >> 7;
    int utid = tid & 127;
    float* sA = sm + half * (32*132);

    unsigned ep = 0;

    for (int t = 0; t <= T; t++) {
        // ---- P1: ctx[t] (+ h0 at t=0) + rored(t-2) ----
        if (t == 0) {
            if (bid < 256) h0_task(hidden, W_init, b_init, sm);
        } else {
            if (bid < 256) ctx_task(t, bid, enc, out, sm);
            else if (t >= 2 && bid < 288) rored_task(t-2, bid - 256, b_read, out);
        }
        ep++; gbar(ep * NBLK);
        if (t == T) break;

        // ---- P2: gx + gh (576 units, stable mapping -> L1-resident weights) --
        if (bid < 288) {
            int unit = bid*2 + half;
            if (unit < 384) gemm_tile(0, t, unit & 7, (unit >> 3) * 32, utid,
                                      Wx, Wh, W_read, sA);
            else {
                int u = unit - 384;
                gemm_tile(1, t, u & 3, (u >> 2) * 32, utid, Wx, Wh, W_read, sA);
            }
        }
        ep++; gbar(ep * NBLK);

        // ---- P3: attn(t) on blocks 0..31 ; ro(t-1) on blocks 32..127 ----
        if (bid < 32) {
            attn_task(t, bid, src_seq, Wq, w_cov, v_att, W_copy, b_copy,
                      bx, bh, out, sm);
        } else if (t >= 1 && bid < 128) {
            int r = (bid - 32)*2 + half;     // 0..191
            gemm_tile(2, t-1, r % 12, (r / 12) * 32, utid, Wx, Wh, W_read, sA);
        }
        ep++; gbar(ep * NBLK);
    }

    // ---- tail: ro(T-1), then rored(T-1) ----
    if (bid >= 32 && bid < 128) {
        int r = (bid - 32)*2 + half;
        gemm_tile(2, T-1, r % 12, (r / 12) * 32, utid, Wx, Wh, W_read, sA);
    }
    ep++; gbar(ep * NBLK);
    if (bid < 32) rored_task(T-1, bid, b_read, out);
}

// ---------------- launch ------------------------------------------------------

extern "C" void kernel_launch(void* const* d_in, const int* in_sizes, int n_in,
                              void* d_out, int out_size)
{
    const int*   tgt      = (const int*)  d_in[0];
    const int*   src      = (const int*)  d_in[1];
    const float* enc      = (const float*)d_in[2];
    const float* hidden   = (const float*)d_in[3];
    const float* word_emb = (const float*)d_in[4];
    const float* W_init   = (const float*)d_in[5];
    const float* b_init   = (const float*)d_in[6];
    const float* Wx       = (const float*)d_in[7];
    const float* Wh       = (const float*)d_in[8];
    const float* bx       = (const float*)d_in[9];
    const float* bh       = (const float*)d_in[10];
    const float* Wc       = (const float*)d_in[11];
    const float* Wq       = (const float*)d_in[12];
    const float* w_cov    = (const float*)d_in[13];
    const float* v_att    = (const float*)d_in[14];
    const float* W_copy   = (const float*)d_in[15];
    const float* b_copy   = (const float*)d_in[16];
    const float* W_read   = (const float*)d_in[17];
    const float* b_read   = (const float*)d_in[18];
    float* out = (float*)d_out;

    k_embed<<<T*B, 128>>>(tgt, word_emb);
    k_pre<<<(B*S)/16, dim3(16,16)>>>(enc, Wc);
    k_encw<<<(B*S)/8, 256>>>(enc, W_copy);
    k_init0<<<64, 256>>>();

    k_persist<<<NBLK, 256, 2*32*132*sizeof(float)>>>(
        src, enc, hidden, W_init, b_init, Wx, Wh, bx, bh,
        Wq, w_cov, v_att, W_copy, b_copy, W_read, b_read, out);
}